// round 3
// baseline (speedup 1.0000x reference)
#include <cuda_runtime.h>
#include <cuda_bf16.h>

// Problem constants
static constexpr int KN = 50000;   // nodes
static constexpr int KE = 150000;  // edges
// dims: IN=16, HID=32, LAT=16, EF=8, HE=128

// ---------------- device scratch (static, no allocation) ----------------
// 16B-aligned so float4 zero-stores are legal.
__device__ __align__(16) float g_agg[KN * 32];
__device__ __align__(16) float g_h1[KN * 32];
__device__ __align__(16) float g_h2[KN * 32];
__device__ __align__(16) int   g_deg[KN];

// ---------------- f32x2 packed helpers (Blackwell FFMA2) ----------------
__device__ __forceinline__ unsigned long long pack2(float x, float y) {
    unsigned long long r;
    asm("mov.b64 %0, {%1, %2};" : "=l"(r) : "f"(x), "f"(y));
    return r;
}
__device__ __forceinline__ void unpack2(unsigned long long v, float& lo, float& hi) {
    asm("mov.b64 {%0, %1}, %2;" : "=f"(lo), "=f"(hi) : "l"(v));
}
__device__ __forceinline__ unsigned long long ffma2(unsigned long long a,
                                                    unsigned long long b,
                                                    unsigned long long c) {
    unsigned long long d;
    asm("fma.rn.f32x2 %0, %1, %2, %3;" : "=l"(d) : "l"(a), "l"(b), "l"(c));
    return d;
}
__device__ __forceinline__ unsigned long long mul2(unsigned long long a,
                                                   unsigned long long b) {
    unsigned long long d;
    asm("mul.rn.f32x2 %0, %1, %2;" : "=l"(d) : "l"(a), "l"(b));
    return d;
}

// ---------------- zeroing (graph-safe; no memset nodes on device symbols) ----
__global__ void zero_f_kernel(float* __restrict__ p, int n) {
    int i = blockIdx.x * 256 + threadIdx.x;
    int i4 = i * 4;
    if (i4 + 3 < n) {
        *(float4*)(p + i4) = make_float4(0.f, 0.f, 0.f, 0.f);
    } else {
        for (int k = i4; k < n; k++) p[k] = 0.f;
    }
}
__global__ void zero_i_kernel(int* __restrict__ p, int n) {
    int i = blockIdx.x * 256 + threadIdx.x;
    if (i < n) p[i] = 0;
}

// ---------------- degree (in-degree by dst) ----------------
// edge_index is int32: JAX with x64 disabled downcasts the reference's int64.
__global__ void deg_kernel(const int* __restrict__ dst) {
    int i = blockIdx.x * 256 + threadIdx.x;
    if (i < KE) atomicAdd(&g_deg[dst[i]], 1);
}

// ---------------- fused edge kernel ----------------
// msg[e,o] = sum_i x[src_e,i] * ( sum_k h[e,k]*w2[k, i*DOUT+o] + b2[i*DOUT+o] )
// with h[e,k] = relu(ea[e]@w1 + b1)[k], scattered via atomicAdd into agg[dst_e].
template <int DIN, int DOUT>
__global__ __launch_bounds__(256)
void edge_kernel(const float* __restrict__ xin,
                 const float* __restrict__ ea,
                 const int* __restrict__ src,
                 const int* __restrict__ dst,
                 const float* __restrict__ w1,
                 const float* __restrict__ b1,
                 const float* __restrict__ w2,
                 const float* __restrict__ b2,
                 float* __restrict__ agg) {
    constexpr int TE = 128;           // edges per block
    constexpr int HP = 129;           // padded pitch for h (conflict-free)
    constexpr int OHALF = DOUT / 2;   // outputs per thread
    constexpr int NP = OHALF / 2;     // f32x2 accumulators per thread
    constexpr int CH = 8192;          // floats per w2 smem chunk (32 KB)
    constexpr int KC = CH / (DIN * DOUT);  // k's per chunk (8 or 16)
    constexpr int NCH = 128 / KC;

    extern __shared__ float sh[];
    float* sh_h  = sh;                       // TE*HP
    float* sh_w2 = sh_h + TE * HP;           // CH (16B aligned: 16512*4 % 16 == 0)
    float* sh_w1 = sh_w2 + CH;               // 8*128
    float* sh_b1 = sh_w1 + 1024;             // 128
    float* sh_b2 = sh_b1 + 128;              // DIN*DOUT
    float* sh_ea = sh_b2 + DIN * DOUT;       // TE*8

    const int tid = threadIdx.x;
    const int e0 = blockIdx.x * TE;

    // cooperative loads of small params + edge_attr tile
    for (int i = tid; i < 1024; i += 256) sh_w1[i] = w1[i];
    for (int i = tid; i < 128; i += 256) sh_b1[i] = b1[i];
    for (int i = tid; i < DIN * DOUT; i += 256) sh_b2[i] = b2[i];
    for (int i = tid; i < TE * 8; i += 256) {
        int g = e0 * 8 + i;
        sh_ea[i] = (g < KE * 8) ? ea[g] : 0.f;
    }
    __syncthreads();

    // edge MLP hidden: h[e][k] = relu(b1[k] + ea[e]@w1[:,k])
    for (int idx = tid; idx < TE * 128; idx += 256) {
        int e = idx >> 7, k = idx & 127;
        float s = sh_b1[k];
#pragma unroll
        for (int j = 0; j < 8; j++) s = fmaf(sh_ea[e * 8 + j], sh_w1[j * 128 + k], s);
        sh_h[e * HP + k] = fmaxf(s, 0.f);
    }
    // (ordering of sh_h writes vs reads is covered by the sync after the
    //  first w2 chunk load below)

    const int e = tid & (TE - 1);
    const int half = tid >> 7;
    const int OB = half * OHALF;
    const bool act = (e0 + e) < KE;

    // gather source features into registers, pre-packed (v,v)
    unsigned long long xs2[DIN];
    {
        int sv = act ? src[e0 + e] : 0;
        const float* xr = xin + (long long)sv * DIN;
#pragma unroll
        for (int i = 0; i < DIN; i++) {
            float v = act ? xr[i] : 0.f;
            xs2[i] = pack2(v, v);
        }
    }

    unsigned long long accv[NP];
#pragma unroll
    for (int p = 0; p < NP; p++) accv[p] = pack2(0.f, 0.f);

    for (int c = 0; c < NCH; c++) {
        // stream w2 chunk into smem
        const float4* gw = (const float4*)(w2 + c * CH);
        float4* sw = (float4*)sh_w2;
        for (int i = tid; i < CH / 4; i += 256) sw[i] = gw[i];
        __syncthreads();

        for (int kk = 0; kk < KC; kk++) {
            float hv = sh_h[e * HP + c * KC + kk];
            unsigned long long hv2 = pack2(hv, hv);
            const float* wrow = sh_w2 + kk * (DIN * DOUT) + OB;
#pragma unroll
            for (int i = 0; i < DIN; i++) {
                unsigned long long av = mul2(xs2[i], hv2);
                const ulonglong2* wp = (const ulonglong2*)(wrow + i * DOUT);
#pragma unroll
                for (int q = 0; q < NP / 2; q++) {
                    ulonglong2 w = wp[q];
                    accv[2 * q]     = ffma2(av, w.x, accv[2 * q]);
                    accv[2 * q + 1] = ffma2(av, w.y, accv[2 * q + 1]);
                }
            }
        }
        __syncthreads();
    }

    // b2 contribution: msg += x[src] @ b2(reshaped DIN x DOUT)
#pragma unroll
    for (int i = 0; i < DIN; i++) {
        const ulonglong2* bp = (const ulonglong2*)(sh_b2 + i * DOUT + OB);
#pragma unroll
        for (int q = 0; q < NP / 2; q++) {
            ulonglong2 w = bp[q];
            accv[2 * q]     = ffma2(xs2[i], w.x, accv[2 * q]);
            accv[2 * q + 1] = ffma2(xs2[i], w.y, accv[2 * q + 1]);
        }
    }

    if (act) {
        int dv = dst[e0 + e];
        float* ap = agg + (long long)dv * DOUT + OB;
#pragma unroll
        for (int p = 0; p < NP; p++) {
            float lo, hi;
            unpack2(accv[p], lo, hi);
            atomicAdd(ap + 2 * p, lo);
            atomicAdd(ap + 2 * p + 1, hi);
        }
    }
}

// ---------------- node epilogue: mean + root GEMM + bias (+relu) ----------------
template <int DIN, int DOUT, bool MEAN, bool RELU>
__global__ __launch_bounds__(256)
void node_kernel(const float* __restrict__ xin,
                 const float* __restrict__ agg,
                 const float* __restrict__ root,
                 const float* __restrict__ bias,
                 const int* __restrict__ deg,
                 float* __restrict__ out) {
    __shared__ float sroot[DIN * DOUT];
    __shared__ float sbias[DOUT];
    int tid = threadIdx.x;
    for (int i = tid; i < DIN * DOUT; i += 256) sroot[i] = root[i];
    if (tid < DOUT) sbias[tid] = bias[tid];
    __syncthreads();

    int idx = blockIdx.x * 256 + tid;
    if (idx >= KN * DOUT) return;
    int n = idx / DOUT, o = idx % DOUT;

    float v = agg[idx];
    if (MEAN) {
        int d = deg[n];
        v *= 1.f / (d > 0 ? (float)d : 1.f);
    }
    const float* xr = xin + n * DIN;
#pragma unroll
    for (int i = 0; i < DIN; i++) v = fmaf(xr[i], sroot[i * DOUT + o], v);
    v += sbias[o];
    if (RELU) v = fmaxf(v, 0.f);
    out[idx] = v;
}

// ---------------- launch ----------------
static constexpr int smem_bytes(int DIN, int DOUT) {
    return (128 * 129 + 8192 + 1024 + 128 + DIN * DOUT + 128 * 8) * 4;
}

extern "C" void kernel_launch(void* const* d_in, const int* in_sizes, int n_in,
                              void* d_out, int out_size) {
    const float* x = (const float*)d_in[0];
    const int* ei = (const int*)d_in[1];   // int32! (JAX x64-disabled downcast)
    const float* ea = (const float*)d_in[2];
    auto f = [&](int i) { return (const float*)d_in[i]; };
    float* out = (float*)d_out;

    const int* src = ei;
    const int* dstp = ei + KE;

    void *agg_p, *deg_p, *h1_p, *h2_p;
    cudaGetSymbolAddress(&agg_p, g_agg);
    cudaGetSymbolAddress(&deg_p, g_deg);
    cudaGetSymbolAddress(&h1_p, g_h1);
    cudaGetSymbolAddress(&h2_p, g_h2);

    cudaFuncSetAttribute(edge_kernel<16, 32>,
                         cudaFuncAttributeMaxDynamicSharedMemorySize, smem_bytes(16, 32));
    cudaFuncSetAttribute(edge_kernel<32, 32>,
                         cudaFuncAttributeMaxDynamicSharedMemorySize, smem_bytes(32, 32));
    cudaFuncSetAttribute(edge_kernel<32, 16>,
                         cudaFuncAttributeMaxDynamicSharedMemorySize, smem_bytes(32, 16));

    const int EB = (KE + 127) / 128;
    const int ZB32 = (KN * 32 / 4 + 255) / 256;  // zero blocks for 32-wide agg
    const int ZB16 = (KN * 16 / 4 + 255) / 256;

    // degree histogram (shared by conv1/conv2 mean)
    zero_i_kernel<<<(KN + 255) / 256, 256>>>((int*)deg_p, KN);
    deg_kernel<<<(KE + 255) / 256, 256>>>(dstp);

    // conv1: IN=16 -> HID=32, mean, relu
    zero_f_kernel<<<ZB32, 256>>>((float*)agg_p, KN * 32);
    edge_kernel<16, 32><<<EB, 256, smem_bytes(16, 32)>>>(
        x, ea, src, dstp, f(3), f(4), f(5), f(6), (float*)agg_p);
    node_kernel<16, 32, true, true><<<(KN * 32 + 255) / 256, 256>>>(
        x, (const float*)agg_p, f(7), f(8), (const int*)deg_p, (float*)h1_p);

    // conv2: 32 -> 32, mean, relu
    zero_f_kernel<<<ZB32, 256>>>((float*)agg_p, KN * 32);
    edge_kernel<32, 32><<<EB, 256, smem_bytes(32, 32)>>>(
        (const float*)h1_p, ea, src, dstp, f(9), f(10), f(11), f(12), (float*)agg_p);
    node_kernel<32, 32, true, true><<<(KN * 32 + 255) / 256, 256>>>(
        (const float*)h1_p, (const float*)agg_p, f(13), f(14), (const int*)deg_p,
        (float*)h2_p);

    // mu: 32 -> 16, sum, no relu  -> out[0 : N*16]
    zero_f_kernel<<<ZB16, 256>>>((float*)agg_p, KN * 16);
    edge_kernel<32, 16><<<EB, 256, smem_bytes(32, 16)>>>(
        (const float*)h2_p, ea, src, dstp, f(15), f(16), f(17), f(18), (float*)agg_p);
    node_kernel<32, 16, false, false><<<(KN * 16 + 255) / 256, 256>>>(
        (const float*)h2_p, (const float*)agg_p, f(19), f(20), (const int*)deg_p, out);

    // logvar: 32 -> 16, sum, no relu -> out[N*16 : 2*N*16]
    zero_f_kernel<<<ZB16, 256>>>((float*)agg_p, KN * 16);
    edge_kernel<32, 16><<<EB, 256, smem_bytes(32, 16)>>>(
        (const float*)h2_p, ea, src, dstp, f(21), f(22), f(23), f(24), (float*)agg_p);
    node_kernel<32, 16, false, false><<<(KN * 16 + 255) / 256, 256>>>(
        (const float*)h2_p, (const float*)agg_p, f(25), f(26), (const int*)deg_p,
        out + KN * 16);
}

// round 4
// speedup vs baseline: 1.2642x; 1.2642x over previous
#include <cuda_runtime.h>
#include <cuda_bf16.h>

// Problem constants
static constexpr int KN = 50000;   // nodes
static constexpr int KE = 150000;  // edges
// dims: IN=16, HID=32, LAT=16, EF=8, HE=128

// ---------------- device scratch (static, no allocation) ----------------
__device__ __align__(16) float g_agg[KN * 32];
__device__ __align__(16) float g_h1[KN * 32];
__device__ __align__(16) float g_h2[KN * 32];
__device__ __align__(16) int   g_deg[KN];

// ---------------- f32x2 packed helpers (Blackwell FFMA2) ----------------
__device__ __forceinline__ unsigned long long pack2(float x, float y) {
    unsigned long long r;
    asm("mov.b64 %0, {%1, %2};" : "=l"(r) : "f"(x), "f"(y));
    return r;
}
__device__ __forceinline__ void unpack2(unsigned long long v, float& lo, float& hi) {
    asm("mov.b64 {%0, %1}, %2;" : "=f"(lo), "=f"(hi) : "l"(v));
}
__device__ __forceinline__ unsigned long long ffma2(unsigned long long a,
                                                    unsigned long long b,
                                                    unsigned long long c) {
    unsigned long long d;
    asm("fma.rn.f32x2 %0, %1, %2, %3;" : "=l"(d) : "l"(a), "l"(b), "l"(c));
    return d;
}
__device__ __forceinline__ unsigned long long mul2(unsigned long long a,
                                                   unsigned long long b) {
    unsigned long long d;
    asm("mul.rn.f32x2 %0, %1, %2;" : "=l"(d) : "l"(a), "l"(b));
    return d;
}

// ---------------- zeroing (graph-safe) ----------------
__global__ void zero_f_kernel(float* __restrict__ p, int n) {
    int i = blockIdx.x * 256 + threadIdx.x;
    int i4 = i * 4;
    if (i4 + 3 < n) {
        *(float4*)(p + i4) = make_float4(0.f, 0.f, 0.f, 0.f);
    } else {
        for (int k = i4; k < n; k++) p[k] = 0.f;
    }
}
__global__ void zero_i_kernel(int* __restrict__ p, int n) {
    int i = blockIdx.x * 256 + threadIdx.x;
    if (i < n) p[i] = 0;
}

// ---------------- degree (in-degree by dst), edge_index is int32 ----------------
__global__ void deg_kernel(const int* __restrict__ dst) {
    int i = blockIdx.x * 256 + threadIdx.x;
    if (i < KE) atomicAdd(&g_deg[dst[i]], 1);
}

// ---------------- fused edge kernel, v2 ----------------
// Layout: lane = output column (OLANE), f32x2 lanes = edge PAIRS.
// Per warp: EPW = 8*(32/DOUT) edges as pairs; w2 read with unique-per-lane
// LDS.32 (1 wavefront per 32 floats) instead of broadcast LDS.128 (4 wf/16B).
// Chunked over k (KR=8): h pairs register-cached, reused across all DIN i's;
// x-multiply folded once per (chunk, i): msg = sum_c sum_i x_i * (sum_k h_k w_kio).
template <int DIN, int DOUT, int TE>
__global__ __launch_bounds__(256, 1)
void edge_kernel(const float* __restrict__ xin,
                 const float* __restrict__ ea,
                 const int* __restrict__ src,
                 const int* __restrict__ dst,
                 const float* __restrict__ w1,
                 const float* __restrict__ b1,
                 const float* __restrict__ w2,
                 const float* __restrict__ b2,
                 float* __restrict__ agg) {
    constexpr int EPW = 8 * (32 / DOUT);   // edges per warp
    constexpr int KSTRIDE = 256 / TE;      // staging stride over k / i
    constexpr int WCH = 8 * DIN * DOUT;    // floats per w2 chunk (KR=8 k's)

    extern __shared__ float sh[];
    float* sw2  = sh;                      // WCH        (16B aligned base)
    float* sh_h = sw2 + WCH;               // 128*TE     (transposed: [k][e])
    float* sx   = sh_h + 128 * TE;         // DIN*TE     (transposed: [i][e])
    float* sea  = sx + DIN * TE;           // TE*8
    float* sw1  = sea + TE * 8;            // 1024
    float* sb1  = sw1 + 1024;              // 128
    float* sb2  = sb1 + 128;               // DIN*DOUT

    const int tid = threadIdx.x;
    const int e0 = blockIdx.x * TE;

    // ---- stage small params + edge_attr tile ----
    for (int i = tid; i < 1024; i += 256) sw1[i] = w1[i];
    if (tid < 128) sb1[tid] = b1[tid];
    for (int i = tid; i < DIN * DOUT; i += 256) sb2[i] = b2[i];
    for (int i = tid; i < TE * 8; i += 256) {
        long long g = (long long)e0 * 8 + i;
        sea[i] = (g < (long long)KE * 8) ? ea[g] : 0.f;
    }
    __syncthreads();

    // ---- edge MLP (h transposed [k][e]) + x staging (transposed [i][e]) ----
    {
        const int me = tid % TE;
        float ear[8];
#pragma unroll
        for (int j = 0; j < 8; j++) ear[j] = sea[me * 8 + j];
        for (int k = tid / TE; k < 128; k += KSTRIDE) {
            float s = sb1[k];
#pragma unroll
            for (int j = 0; j < 8; j++) s = fmaf(ear[j], sw1[j * 128 + k], s);
            sh_h[k * TE + me] = fmaxf(s, 0.f);
        }
        const bool actx = (e0 + me) < KE;
        const int sv = actx ? src[e0 + me] : 0;
        for (int i = tid / TE; i < DIN; i += KSTRIDE) {
            sx[i * TE + me] = actx ? xin[(long long)sv * DIN + i] : 0.f;
        }
    }
    __syncthreads();

    const int lane = tid & 31, warp = tid >> 5;
    const int OLANE = lane % DOUT;
    const int EB = warp * EPW + (lane / DOUT) * 8;  // local edge base, 4 pairs

    unsigned long long msg[4] = {0ull, 0ull, 0ull, 0ull};

    for (int c = 0; c < 16; c++) {
        // stage w2 chunk (k = 8c .. 8c+7)
        {
            const float4* gw = (const float4*)(w2 + c * WCH);
            float4* dw = (float4*)sw2;
            for (int i2 = tid; i2 < WCH / 4; i2 += 256) dw[i2] = gw[i2];
        }
        __syncthreads();

        // register-cache h pairs for this chunk (broadcast LDS.64)
        unsigned long long hp[4][8];
#pragma unroll
        for (int p = 0; p < 4; p++)
#pragma unroll
            for (int kk = 0; kk < 8; kk++)
                hp[p][kk] =
                    *(const unsigned long long*)(sh_h + (c * 8 + kk) * TE + EB + 2 * p);

#pragma unroll 1
        for (int i = 0; i < DIN; i++) {
            // unique-per-lane w loads: 1 wavefront each
            float wv[8];
#pragma unroll
            for (int kk = 0; kk < 8; kk++)
                wv[kk] = sw2[kk * DIN * DOUT + i * DOUT + OLANE];

            unsigned long long acc[4];
            {
                unsigned long long wd = pack2(wv[0], wv[0]);
#pragma unroll
                for (int p = 0; p < 4; p++) acc[p] = mul2(hp[p][0], wd);
            }
#pragma unroll
            for (int kk = 1; kk < 8; kk++) {
                unsigned long long wd = pack2(wv[kk], wv[kk]);
#pragma unroll
                for (int p = 0; p < 4; p++) acc[p] = ffma2(hp[p][kk], wd, acc[p]);
            }
            // fold: msg += x[:,i] * acc_i
#pragma unroll
            for (int p = 0; p < 4; p++) {
                unsigned long long xp =
                    *(const unsigned long long*)(sx + i * TE + EB + 2 * p);
                msg[p] = ffma2(xp, acc[p], msg[p]);
            }
        }
        __syncthreads();
    }

    // ---- b2 term: msg += x @ b2(reshaped DIN x DOUT) ----
#pragma unroll 1
    for (int i = 0; i < DIN; i++) {
        float bv = sb2[i * DOUT + OLANE];
        unsigned long long bd = pack2(bv, bv);
#pragma unroll
        for (int p = 0; p < 4; p++) {
            unsigned long long xp =
                *(const unsigned long long*)(sx + i * TE + EB + 2 * p);
            msg[p] = ffma2(xp, bd, msg[p]);
        }
    }

    // ---- scatter (atomics, one column per lane, 2 edges per pair) ----
#pragma unroll
    for (int p = 0; p < 4; p++) {
        float lo, hi;
        unpack2(msg[p], lo, hi);
        int ge = e0 + EB + 2 * p;
        if (ge < KE)
            atomicAdd(agg + (long long)dst[ge] * DOUT + OLANE, lo);
        if (ge + 1 < KE)
            atomicAdd(agg + (long long)dst[ge + 1] * DOUT + OLANE, hi);
    }
}

// ---------------- node epilogue: mean + root GEMM + bias (+relu) ----------------
template <int DIN, int DOUT, bool MEAN, bool RELU>
__global__ __launch_bounds__(256)
void node_kernel(const float* __restrict__ xin,
                 const float* __restrict__ agg,
                 const float* __restrict__ root,
                 const float* __restrict__ bias,
                 const int* __restrict__ deg,
                 float* __restrict__ out) {
    __shared__ float sroot[DIN * DOUT];
    __shared__ float sbias[DOUT];
    int tid = threadIdx.x;
    for (int i = tid; i < DIN * DOUT; i += 256) sroot[i] = root[i];
    if (tid < DOUT) sbias[tid] = bias[tid];
    __syncthreads();

    int idx = blockIdx.x * 256 + tid;
    if (idx >= KN * DOUT) return;
    int n = idx / DOUT, o = idx % DOUT;

    float v = agg[idx];
    if (MEAN) {
        int d = deg[n];
        v *= 1.f / (d > 0 ? (float)d : 1.f);
    }
    const float* xr = xin + n * DIN;
#pragma unroll
    for (int i = 0; i < DIN; i++) v = fmaf(xr[i], sroot[i * DOUT + o], v);
    v += sbias[o];
    if (RELU) v = fmaxf(v, 0.f);
    out[idx] = v;
}

// ---------------- launch ----------------
static constexpr int smem_bytes2(int DIN, int DOUT, int TE) {
    return (8 * DIN * DOUT + 128 * TE + DIN * TE + TE * 8 + 1024 + 128 +
            DIN * DOUT) * 4;
}

extern "C" void kernel_launch(void* const* d_in, const int* in_sizes, int n_in,
                              void* d_out, int out_size) {
    const float* x = (const float*)d_in[0];
    const int* ei = (const int*)d_in[1];  // int32 (JAX x64-disabled downcast)
    const float* ea = (const float*)d_in[2];
    auto f = [&](int i) { return (const float*)d_in[i]; };
    float* out = (float*)d_out;

    const int* src = ei;
    const int* dstp = ei + KE;

    void *agg_p, *deg_p, *h1_p, *h2_p;
    cudaGetSymbolAddress(&agg_p, g_agg);
    cudaGetSymbolAddress(&deg_p, g_deg);
    cudaGetSymbolAddress(&h1_p, g_h1);
    cudaGetSymbolAddress(&h2_p, g_h2);

    cudaFuncSetAttribute(edge_kernel<16, 32, 64>,
                         cudaFuncAttributeMaxDynamicSharedMemorySize,
                         smem_bytes2(16, 32, 64));
    cudaFuncSetAttribute(edge_kernel<32, 32, 64>,
                         cudaFuncAttributeMaxDynamicSharedMemorySize,
                         smem_bytes2(32, 32, 64));
    cudaFuncSetAttribute(edge_kernel<32, 16, 128>,
                         cudaFuncAttributeMaxDynamicSharedMemorySize,
                         smem_bytes2(32, 16, 128));

    const int EB64 = (KE + 63) / 64;
    const int EB128 = (KE + 127) / 128;
    const int ZB32 = (KN * 32 / 4 + 255) / 256;
    const int ZB16 = (KN * 16 / 4 + 255) / 256;

    // degree histogram (shared by conv1/conv2 mean)
    zero_i_kernel<<<(KN + 255) / 256, 256>>>((int*)deg_p, KN);
    deg_kernel<<<(KE + 255) / 256, 256>>>(dstp);

    // conv1: IN=16 -> HID=32, mean, relu
    zero_f_kernel<<<ZB32, 256>>>((float*)agg_p, KN * 32);
    edge_kernel<16, 32, 64><<<EB64, 256, smem_bytes2(16, 32, 64)>>>(
        x, ea, src, dstp, f(3), f(4), f(5), f(6), (float*)agg_p);
    node_kernel<16, 32, true, true><<<(KN * 32 + 255) / 256, 256>>>(
        x, (const float*)agg_p, f(7), f(8), (const int*)deg_p, (float*)h1_p);

    // conv2: 32 -> 32, mean, relu
    zero_f_kernel<<<ZB32, 256>>>((float*)agg_p, KN * 32);
    edge_kernel<32, 32, 64><<<EB64, 256, smem_bytes2(32, 32, 64)>>>(
        (const float*)h1_p, ea, src, dstp, f(9), f(10), f(11), f(12),
        (float*)agg_p);
    node_kernel<32, 32, true, true><<<(KN * 32 + 255) / 256, 256>>>(
        (const float*)h1_p, (const float*)agg_p, f(13), f(14), (const int*)deg_p,
        (float*)h2_p);

    // mu: 32 -> 16, sum, no relu  -> out[0 : N*16]
    zero_f_kernel<<<ZB16, 256>>>((float*)agg_p, KN * 16);
    edge_kernel<32, 16, 128><<<EB128, 256, smem_bytes2(32, 16, 128)>>>(
        (const float*)h2_p, ea, src, dstp, f(15), f(16), f(17), f(18),
        (float*)agg_p);
    node_kernel<32, 16, false, false><<<(KN * 16 + 255) / 256, 256>>>(
        (const float*)h2_p, (const float*)agg_p, f(19), f(20), (const int*)deg_p,
        out);

    // logvar: 32 -> 16, sum, no relu -> out[N*16 : 2*N*16]
    zero_f_kernel<<<ZB16, 256>>>((float*)agg_p, KN * 16);
    edge_kernel<32, 16, 128><<<EB128, 256, smem_bytes2(32, 16, 128)>>>(
        (const float*)h2_p, ea, src, dstp, f(21), f(22), f(23), f(24),
        (float*)agg_p);
    node_kernel<32, 16, false, false><<<(KN * 16 + 255) / 256, 256>>>(
        (const float*)h2_p, (const float*)agg_p, f(25), f(26), (const int*)deg_p,
        out + KN * 16);
}